// round 2
// baseline (speedup 1.0000x reference)
#include <cuda_runtime.h>

// Problem constants (B=16, C=64, H=W=128, heads=4)
#define NBH    64        // B * heads
#define CPH    16        // channels per head
#define HW     16384     // H * W
#define SPLITS 16
#define KSPL   1024      // HW / SPLITS
#define TILE   128
#define NT     (KSPL / TILE)      // tiles per block = 8
#define SSTR   130       // smem row stride (floats): bank = (2*row + k) % 32
#define BUFSZ  (2 * CPH * SSTR)   // 4160 floats per buffer

// Scratch (no cudaMalloc allowed)
__device__ float g_scr[SPLITS][NBH][288];   // per-(split,bh): 256 gram + 16 nx + 16 ny
__device__ float g_M1[NBH][256];            // t1 * attn1[c][d]
__device__ float g_M2[NBH][256];            // t2 * attn2[c][d]

// ---------------------------------------------------------------------------
// Kernel 1: per (split, bh) partial Gram matrix + row sum-of-squares.
// Software-pipelined: register prefetch of next tile overlaps compute,
// double-buffered smem -> single barrier per tile.
// ---------------------------------------------------------------------------
__global__ __launch_bounds__(256, 2) void k_gram(const float* __restrict__ x,
                                                 const float* __restrict__ y) {
    const int s  = blockIdx.x;
    const int bh = blockIdx.y;
    const float* xb = x + (size_t)bh * CPH * HW;
    const float* yb = y + (size_t)bh * CPH * HW;

    __shared__ float sbuf[2 * BUFSZ];

    const int t  = threadIdx.x;
    const int pg = t & 3;          // which 8x8 quadrant of the 16x16 pair space
    const int kp = t >> 2;         // k phase 0..63
    const int c0 = (pg >> 1) << 3; // 0 or 8
    const int d0 = (pg & 1) << 3;  // 0 or 8

    float acc[8][8];
#pragma unroll
    for (int i = 0; i < 8; i++)
#pragma unroll
        for (int j = 0; j < 8; j++) acc[i][j] = 0.f;
    float nxa[8], nya[8];
#pragma unroll
    for (int i = 0; i < 8; i++) { nxa[i] = 0.f; nya[i] = 0.f; }

    // Staging layout: thread t stages float2 at (row = 4r' + (t>>6), q = t&63)
    // for r' = 0..3, once for x and once for y.
    const int rbm = t >> 6;
    const int q2  = (t & 63) * 2;
    int goff[4], soff[4];
#pragma unroll
    for (int r = 0; r < 4; r++) {
        const int row = 4 * r + rbm;
        goff[r] = row * HW + q2;
        soff[r] = row * SSTR + q2;
    }

    const int kbase = s * KSPL;
    int kpos = kbase;

    // Prefetch tile 0
    float2 st[8];
#pragma unroll
    for (int r = 0; r < 4; r++) {
        st[r]     = *reinterpret_cast<const float2*>(xb + goff[r] + kpos);
        st[4 + r] = *reinterpret_cast<const float2*>(yb + goff[r] + kpos);
    }

    for (int tile = 0; tile < NT; ++tile) {
        float* xs = sbuf + (tile & 1) * BUFSZ;
        float* ys = xs + CPH * SSTR;
        // Store staged tile (other buffer than the one still being read by
        // laggards of compute(tile-1); the single barrier below orders
        // STS(tile) before compute(tile) and, transitively, compute(tile-1)
        // before STS(tile+1)).
#pragma unroll
        for (int r = 0; r < 4; r++) {
            *reinterpret_cast<float2*>(xs + soff[r]) = st[r];
            *reinterpret_cast<float2*>(ys + soff[r]) = st[4 + r];
        }
        __syncthreads();

        kpos += TILE;
        if (tile + 1 < NT) {   // prefetch next tile; LDG latency hides under compute
#pragma unroll
            for (int r = 0; r < 4; r++) {
                st[r]     = *reinterpret_cast<const float2*>(xb + goff[r] + kpos);
                st[4 + r] = *reinterpret_cast<const float2*>(yb + goff[r] + kpos);
            }
        }

#pragma unroll
        for (int u = 0; u < 2; ++u) {
            const int kc = kp + 64 * u;
            float xv[8], yv[8];
#pragma unroll
            for (int i = 0; i < 8; i++) {
                xv[i] = xs[(c0 + i) * SSTR + kc];
                yv[i] = ys[(d0 + i) * SSTR + kc];
            }
#pragma unroll
            for (int i = 0; i < 8; i++)
#pragma unroll
                for (int j = 0; j < 8; j++) acc[i][j] = fmaf(xv[i], yv[j], acc[i][j]);
            if ((pg & 1) == 0) {
#pragma unroll
                for (int i = 0; i < 8; i++) nxa[i] = fmaf(xv[i], xv[i], nxa[i]);
            }
            if ((pg >> 1) == 0) {
#pragma unroll
                for (int i = 0; i < 8; i++) nya[i] = fmaf(yv[i], yv[i], nya[i]);
            }
        }
    }
    __syncthreads();

    // Reduce over the 8 k-phases inside each warp (lane bits 2..4)
#pragma unroll
    for (int m = 4; m <= 16; m <<= 1) {
#pragma unroll
        for (int i = 0; i < 8; i++)
#pragma unroll
            for (int j = 0; j < 8; j++)
                acc[i][j] += __shfl_xor_sync(0xffffffffu, acc[i][j], m);
#pragma unroll
        for (int i = 0; i < 8; i++) {
            nxa[i] += __shfl_xor_sync(0xffffffffu, nxa[i], m);
            nya[i] += __shfl_xor_sync(0xffffffffu, nya[i], m);
        }
    }

    const int w = t >> 5, l = t & 31;
    if (l < 4) {   // l == pg here
#pragma unroll
        for (int i = 0; i < 8; i++)
#pragma unroll
            for (int j = 0; j < 8; j++)
                sbuf[(w * 4 + l) * 64 + i * 8 + j] = acc[i][j];
    }
    if (l == 0 || l == 2) {   // pg 0 / 2 hold nx for c0 = 0 / 8
#pragma unroll
        for (int i = 0; i < 8; i++) sbuf[2048 + w * 16 + c0 + i] = nxa[i];
    }
    if (l == 0 || l == 1) {   // pg 0 / 1 hold ny for d0 = 0 / 8
#pragma unroll
        for (int i = 0; i < 8; i++) sbuf[2176 + w * 16 + d0 + i] = nya[i];
    }
    __syncthreads();

    {   // cross-warp reduce: one thread per (c,d) pair
        const int c = t >> 4, d = t & 15;
        const int pgo = ((c >> 3) << 1) | (d >> 3);
        const int idx = (c & 7) * 8 + (d & 7);
        float sum = 0.f;
#pragma unroll
        for (int ww = 0; ww < 8; ww++) sum += sbuf[(ww * 4 + pgo) * 64 + idx];
        g_scr[s][bh][t] = sum;
    }
    if (t < 16) {
        float sum = 0.f;
#pragma unroll
        for (int ww = 0; ww < 8; ww++) sum += sbuf[2048 + ww * 16 + t];
        g_scr[s][bh][256 + t] = sum;
    } else if (t < 32) {
        const int d = t - 16;
        float sum = 0.f;
#pragma unroll
        for (int ww = 0; ww < 8; ww++) sum += sbuf[2176 + ww * 16 + d];
        g_scr[s][bh][272 + d] = sum;
    }
}

// ---------------------------------------------------------------------------
// Kernel 2: energy, dual softmax, temperature pre-scale
// ---------------------------------------------------------------------------
__global__ __launch_bounds__(256) void k_attn(const float* __restrict__ t1p,
                                              const float* __restrict__ t2p) {
    const int bh = blockIdx.x;
    const int t  = threadIdx.x;
    __shared__ float sE[256];
    __shared__ float sNx[16];
    __shared__ float sNy[16];

    float gsum = 0.f;
#pragma unroll
    for (int s = 0; s < SPLITS; s++) gsum += g_scr[s][bh][t];
    if (t < 16) {
        float nx = 0.f;
#pragma unroll
        for (int s = 0; s < SPLITS; s++) nx += g_scr[s][bh][256 + t];
        sNx[t] = fmaxf(sqrtf(nx), 1e-12f);
    } else if (t < 32) {
        const int d = t - 16;
        float ny = 0.f;
#pragma unroll
        for (int s = 0; s < SPLITS; s++) ny += g_scr[s][bh][272 + d];
        sNy[d] = fmaxf(sqrtf(ny), 1e-12f);
    }
    __syncthreads();

    const int c = t >> 4, d = t & 15;
    const float e = gsum / (sNx[c] * sNy[d]);
    sE[t] = e;

    // attn1: softmax over d (lane low 4 bits)
    float m = e;
#pragma unroll
    for (int msk = 1; msk <= 8; msk <<= 1)
        m = fmaxf(m, __shfl_xor_sync(0xffffffffu, m, msk));
    float p = __expf(e - m);
    float Z = p;
#pragma unroll
    for (int msk = 1; msk <= 8; msk <<= 1)
        Z += __shfl_xor_sync(0xffffffffu, Z, msk);
    g_M1[bh][t] = t1p[0] * (p / Z);

    __syncthreads();
    // attn2[c][d] = exp(e[d][c]) / sum_{d'} exp(e[d'][c])  — column softmax
    const float f = sE[d * 16 + c];
    float m2 = f;
#pragma unroll
    for (int msk = 1; msk <= 8; msk <<= 1)
        m2 = fmaxf(m2, __shfl_xor_sync(0xffffffffu, m2, msk));
    float p2 = __expf(f - m2);
    float Z2 = p2;
#pragma unroll
    for (int msk = 1; msk <= 8; msk <<= 1)
        Z2 += __shfl_xor_sync(0xffffffffu, Z2, msk);
    g_M2[bh][t] = t2p[0] * (p2 / Z2);
}

// ---------------------------------------------------------------------------
// Kernel 3: apply attention + residual + concat
// out[:, 0:64]  = t2 * x_att + y
// out[:, 64:128]= t1 * y_att + x
// 128 threads/block for ~3 CTAs/SM; all 32 float4 loads front-batched.
// ---------------------------------------------------------------------------
__global__ __launch_bounds__(128) void k_apply(const float* __restrict__ x,
                                               const float* __restrict__ y,
                                               float* __restrict__ out) {
    const int bh = blockIdx.y;
    const int kc = blockIdx.x;
    const int t  = threadIdx.x;
    __shared__ float sM1[256];
    __shared__ float sM2[256];
    sM1[t]       = g_M1[bh][t];
    sM1[t + 128] = g_M1[bh][t + 128];
    sM2[t]       = g_M2[bh][t];
    sM2[t + 128] = g_M2[bh][t + 128];
    __syncthreads();

    const int b = bh >> 2, h = bh & 3;
    const int k4 = kc * 128 + t;                 // float4 column index
    const float4* xb = reinterpret_cast<const float4*>(x + (size_t)bh * CPH * HW);
    const float4* yb = reinterpret_cast<const float4*>(y + (size_t)bh * CPH * HW);

    float4 xv[16], yv[16];
#pragma unroll
    for (int c = 0; c < 16; c++) {
        xv[c] = xb[c * (HW / 4) + k4];
        yv[c] = yb[c * (HW / 4) + k4];
    }

    float4* ob = reinterpret_cast<float4*>(out + (size_t)b * 128 * HW);
#pragma unroll
    for (int d = 0; d < 16; d++) {
        float4 ay = xv[d];   // y_ = t1*y_att + x
        float4 ax = yv[d];   // x_ = t2*x_att + y
#pragma unroll
        for (int c = 0; c < 16; c++) {
            const float m1 = sM1[c * 16 + d];
            const float m2 = sM2[c * 16 + d];
            ay.x = fmaf(m1, yv[c].x, ay.x);
            ay.y = fmaf(m1, yv[c].y, ay.y);
            ay.z = fmaf(m1, yv[c].z, ay.z);
            ay.w = fmaf(m1, yv[c].w, ay.w);
            ax.x = fmaf(m2, xv[c].x, ax.x);
            ax.y = fmaf(m2, xv[c].y, ax.y);
            ax.z = fmaf(m2, xv[c].z, ax.z);
            ax.w = fmaf(m2, xv[c].w, ax.w);
        }
        ob[(size_t)(h * 16 + d) * (HW / 4) + k4] = ax;         // channels 0..63
        ob[(size_t)(64 + h * 16 + d) * (HW / 4) + k4] = ay;    // channels 64..127
    }
}

// ---------------------------------------------------------------------------
extern "C" void kernel_launch(void* const* d_in, const int* in_sizes, int n_in,
                              void* d_out, int out_size) {
    const float* x  = (const float*)d_in[0];
    const float* y  = (const float*)d_in[1];
    const float* t1 = (const float*)d_in[2];
    const float* t2 = (const float*)d_in[3];
    float* out = (float*)d_out;

    k_gram<<<dim3(SPLITS, NBH), 256>>>(x, y);
    k_attn<<<NBH, 256>>>(t1, t2);
    k_apply<<<dim3(HW / 4 / 128, NBH), 128>>>(x, y, out);
}

// round 3
// speedup vs baseline: 1.3199x; 1.3199x over previous
#include <cuda_runtime.h>
#include <cstdint>

// Problem constants (B=16, C=64, H=W=128, heads=4)
#define NBH    64        // B * heads
#define CPH    16        // channels per head
#define HW     16384     // H * W
#define SPLITS 8
#define KSPL   2048      // HW / SPLITS
#define HT     64        // k-floats per tile (one float4 per thread phase)
#define NT     (KSPL / HT)        // 32 tiles
#define SSTR   68        // smem row stride (floats): 16B-aligned rows, bank +4/row
#define BUF    (2 * CPH * SSTR)   // 2176 floats per stage (x + y)
#define NBUF   4

// Scratch (no cudaMalloc allowed)
__device__ float g_scr[SPLITS][NBH][288];   // per-(split,bh): 256 gram + 16 nx + 16 ny
__device__ float g_M1[NBH][256];            // t1 * attn1[c][d]
__device__ float g_M2[NBH][256];            // t2 * attn2[c][d]

__device__ __forceinline__ void cp16(uint32_t saddr, const void* gaddr) {
    asm volatile("cp.async.cg.shared.global [%0], [%1], 16;\n" :: "r"(saddr), "l"(gaddr));
}
__device__ __forceinline__ void cp_commit() { asm volatile("cp.async.commit_group;\n"); }
__device__ __forceinline__ void cp_wait1()  { asm volatile("cp.async.wait_group 1;\n" ::: "memory"); }
__device__ __forceinline__ void cp_wait0()  { asm volatile("cp.async.wait_group 0;\n" ::: "memory"); }

// ---------------------------------------------------------------------------
// Kernel 1: per (split, bh) partial Gram + row sum-of-squares.
// cp.async 4-buffer ring, depth-2; 4x4 register tiles; shuffle-only epilogue.
// ---------------------------------------------------------------------------
__global__ __launch_bounds__(256, 4) void k_gram(const float* __restrict__ x,
                                                 const float* __restrict__ y) {
    const int s  = blockIdx.x;
    const int bh = blockIdx.y;
    const float* xb = x + (size_t)bh * CPH * HW;
    const float* yb = y + (size_t)bh * CPH * HW;

    __shared__ float sbuf[NBUF * BUF];

    const int t  = threadIdx.x;
    const int g  = t >> 4;         // 16 quadrant groups (4x4 each)
    const int kp = t & 15;         // float4 k-phase within 64-float tile
    const int c0 = (g >> 2) * 4;
    const int d0 = (g & 3) * 4;

    // Staging: thread t copies one float4 of x and one of y per tile.
    const int srow = t >> 4;       // 16 rows
    const int sq   = t & 15;       // 16 float4 per row
    const uint32_t sb = (uint32_t)__cvta_generic_to_shared(sbuf);
    const uint32_t sOffX = (uint32_t)(srow * SSTR + sq * 4) * 4u;
    const uint32_t sOffY = (uint32_t)((CPH + srow) * SSTR + sq * 4) * 4u;
    const float* gx = xb + srow * HW + sq * 4 + s * KSPL;
    const float* gy = yb + srow * HW + sq * 4 + s * KSPL;

    float acc[4][4];
#pragma unroll
    for (int i = 0; i < 4; i++)
#pragma unroll
        for (int j = 0; j < 4; j++) acc[i][j] = 0.f;
    float nxa[4], nya[4];
#pragma unroll
    for (int i = 0; i < 4; i++) { nxa[i] = 0.f; nya[i] = 0.f; }

    // Prologue: tiles 0 and 1 in flight
#pragma unroll
    for (int p = 0; p < 2; p++) {
        const uint32_t base = sb + (uint32_t)(p * BUF * 4);
        cp16(base + sOffX, gx + p * HT);
        cp16(base + sOffY, gy + p * HT);
        cp_commit();
    }

    for (int tile = 0; tile < NT; ++tile) {
        if (tile == NT - 1) cp_wait0(); else cp_wait1();
        __syncthreads();
        if (tile + 2 < NT) {
            const uint32_t base = sb + (uint32_t)(((tile + 2) & (NBUF - 1)) * BUF * 4);
            cp16(base + sOffX, gx + (tile + 2) * HT);
            cp16(base + sOffY, gy + (tile + 2) * HT);
            cp_commit();
        }

        const float* xs = sbuf + (tile & (NBUF - 1)) * BUF;
        const float* ys = xs + CPH * SSTR;

        float4 xv[4], yv[4];
#pragma unroll
        for (int i = 0; i < 4; i++)
            xv[i] = *reinterpret_cast<const float4*>(xs + (c0 + i) * SSTR + kp * 4);
#pragma unroll
        for (int j = 0; j < 4; j++)
            yv[j] = *reinterpret_cast<const float4*>(ys + (d0 + j) * SSTR + kp * 4);

#pragma unroll
        for (int i = 0; i < 4; i++)
#pragma unroll
            for (int j = 0; j < 4; j++) {
                float a = acc[i][j];
                a = fmaf(xv[i].x, yv[j].x, a);
                a = fmaf(xv[i].y, yv[j].y, a);
                a = fmaf(xv[i].z, yv[j].z, a);
                a = fmaf(xv[i].w, yv[j].w, a);
                acc[i][j] = a;
            }
        if ((g & 3) == 0) {
#pragma unroll
            for (int i = 0; i < 4; i++) {
                float a = nxa[i];
                a = fmaf(xv[i].x, xv[i].x, a);
                a = fmaf(xv[i].y, xv[i].y, a);
                a = fmaf(xv[i].z, xv[i].z, a);
                a = fmaf(xv[i].w, xv[i].w, a);
                nxa[i] = a;
            }
        }
        if (g < 4) {
#pragma unroll
            for (int j = 0; j < 4; j++) {
                float a = nya[j];
                a = fmaf(yv[j].x, yv[j].x, a);
                a = fmaf(yv[j].y, yv[j].y, a);
                a = fmaf(yv[j].z, yv[j].z, a);
                a = fmaf(yv[j].w, yv[j].w, a);
                nya[j] = a;
            }
        }
    }

    // Reduce over the 16 kp phases (lane bits 0..3); each (g,kp) unique -> done.
#pragma unroll
    for (int m = 1; m <= 8; m <<= 1) {
#pragma unroll
        for (int i = 0; i < 4; i++)
#pragma unroll
            for (int j = 0; j < 4; j++)
                acc[i][j] += __shfl_xor_sync(0xffffffffu, acc[i][j], m);
#pragma unroll
        for (int i = 0; i < 4; i++) {
            nxa[i] += __shfl_xor_sync(0xffffffffu, nxa[i], m);
            nya[i] += __shfl_xor_sync(0xffffffffu, nya[i], m);
        }
    }

    if (kp == 0) {
#pragma unroll
        for (int i = 0; i < 4; i++)
#pragma unroll
            for (int j = 0; j < 4; j++)
                g_scr[s][bh][(c0 + i) * 16 + (d0 + j)] = acc[i][j];
        if ((g & 3) == 0) {
#pragma unroll
            for (int i = 0; i < 4; i++) g_scr[s][bh][256 + c0 + i] = nxa[i];
        }
        if (g < 4) {
#pragma unroll
            for (int j = 0; j < 4; j++) g_scr[s][bh][272 + d0 + j] = nya[j];
        }
    }
}

// ---------------------------------------------------------------------------
// Kernel 2: energy, dual softmax, temperature pre-scale
// ---------------------------------------------------------------------------
__global__ __launch_bounds__(256) void k_attn(const float* __restrict__ t1p,
                                              const float* __restrict__ t2p) {
    const int bh = blockIdx.x;
    const int t  = threadIdx.x;
    __shared__ float sE[256];
    __shared__ float sNx[16];
    __shared__ float sNy[16];

    float gsum = 0.f;
#pragma unroll
    for (int s = 0; s < SPLITS; s++) gsum += g_scr[s][bh][t];
    if (t < 16) {
        float nx = 0.f;
#pragma unroll
        for (int s = 0; s < SPLITS; s++) nx += g_scr[s][bh][256 + t];
        sNx[t] = fmaxf(sqrtf(nx), 1e-12f);
    } else if (t < 32) {
        const int d = t - 16;
        float ny = 0.f;
#pragma unroll
        for (int s = 0; s < SPLITS; s++) ny += g_scr[s][bh][272 + d];
        sNy[d] = fmaxf(sqrtf(ny), 1e-12f);
    }
    __syncthreads();

    const int c = t >> 4, d = t & 15;
    const float e = gsum / (sNx[c] * sNy[d]);
    sE[t] = e;

    // attn1: softmax over d (lane low 4 bits)
    float m = e;
#pragma unroll
    for (int msk = 1; msk <= 8; msk <<= 1)
        m = fmaxf(m, __shfl_xor_sync(0xffffffffu, m, msk));
    float p = __expf(e - m);
    float Z = p;
#pragma unroll
    for (int msk = 1; msk <= 8; msk <<= 1)
        Z += __shfl_xor_sync(0xffffffffu, Z, msk);
    g_M1[bh][t] = t1p[0] * (p / Z);

    __syncthreads();
    // attn2[c][d] = softmax over column of energy
    const float f = sE[d * 16 + c];
    float m2 = f;
#pragma unroll
    for (int msk = 1; msk <= 8; msk <<= 1)
        m2 = fmaxf(m2, __shfl_xor_sync(0xffffffffu, m2, msk));
    float p2 = __expf(f - m2);
    float Z2 = p2;
#pragma unroll
    for (int msk = 1; msk <= 8; msk <<= 1)
        Z2 += __shfl_xor_sync(0xffffffffu, Z2, msk);
    g_M2[bh][t] = t2p[0] * (p2 / Z2);
}

// ---------------------------------------------------------------------------
// Kernel 3: apply attention + residual + concat (streaming ld/st hints)
// out[:, 0:64]  = t2 * x_att + y
// out[:, 64:128]= t1 * y_att + x
// ---------------------------------------------------------------------------
__global__ __launch_bounds__(128) void k_apply(const float* __restrict__ x,
                                               const float* __restrict__ y,
                                               float* __restrict__ out) {
    const int bh = blockIdx.y;
    const int kc = blockIdx.x;
    const int t  = threadIdx.x;
    __shared__ float sM1[256];
    __shared__ float sM2[256];
    sM1[t]       = g_M1[bh][t];
    sM1[t + 128] = g_M1[bh][t + 128];
    sM2[t]       = g_M2[bh][t];
    sM2[t + 128] = g_M2[bh][t + 128];
    __syncthreads();

    const int b = bh >> 2, h = bh & 3;
    const int k4 = kc * 128 + t;                 // float4 column index
    const float4* xb = reinterpret_cast<const float4*>(x + (size_t)bh * CPH * HW);
    const float4* yb = reinterpret_cast<const float4*>(y + (size_t)bh * CPH * HW);

    float4 xv[16], yv[16];
#pragma unroll
    for (int c = 0; c < 16; c++) {
        xv[c] = __ldcs(&xb[c * (HW / 4) + k4]);
        yv[c] = __ldcs(&yb[c * (HW / 4) + k4]);
    }

    float4* ob = reinterpret_cast<float4*>(out + (size_t)b * 128 * HW);
#pragma unroll
    for (int d = 0; d < 16; d++) {
        float4 ay = xv[d];   // y_ = t1*y_att + x
        float4 ax = yv[d];   // x_ = t2*x_att + y
#pragma unroll
        for (int c = 0; c < 16; c++) {
            const float m1 = sM1[c * 16 + d];
            const float m2 = sM2[c * 16 + d];
            ay.x = fmaf(m1, yv[c].x, ay.x);
            ay.y = fmaf(m1, yv[c].y, ay.y);
            ay.z = fmaf(m1, yv[c].z, ay.z);
            ay.w = fmaf(m1, yv[c].w, ay.w);
            ax.x = fmaf(m2, xv[c].x, ax.x);
            ax.y = fmaf(m2, xv[c].y, ax.y);
            ax.z = fmaf(m2, xv[c].z, ax.z);
            ax.w = fmaf(m2, xv[c].w, ax.w);
        }
        __stcs(&ob[(size_t)(h * 16 + d) * (HW / 4) + k4], ax);        // ch 0..63
        __stcs(&ob[(size_t)(64 + h * 16 + d) * (HW / 4) + k4], ay);   // ch 64..127
    }
}

// ---------------------------------------------------------------------------
extern "C" void kernel_launch(void* const* d_in, const int* in_sizes, int n_in,
                              void* d_out, int out_size) {
    const float* x  = (const float*)d_in[0];
    const float* y  = (const float*)d_in[1];
    const float* t1 = (const float*)d_in[2];
    const float* t2 = (const float*)d_in[3];
    float* out = (float*)d_out;

    k_gram<<<dim3(SPLITS, NBH), 256>>>(x, y);
    k_attn<<<NBH, 256>>>(t1, t2);
    k_apply<<<dim3(HW / 4 / 128, NBH), 128>>>(x, y, out);
}